// round 2
// baseline (speedup 1.0000x reference)
#include <cuda_runtime.h>
#include <cuda_bf16.h>
#include <math.h>

// Problem dims
#define TT 256
#define BB 16
#define SS 64
#define DD 256
#define GRP 8          // CTAs per batch group (e-split)
#define NC 32          // e-columns per CTA
#define NCTA (BB*GRP)  // 128
#define NTHR 256

#define BSD (BB*SS*DD)     // 262144
#define TBD (TT*BB*DD)     // 1048576

// Scratch (device globals; allocation-free rule)
__device__ float g_wxb[TBD];          // Wx@x + bias, [t][b][e]
__device__ float g_sz[TBD];           // silu(z),    [t][b][e]
__device__ unsigned g_bar[BB];        // monotonic per-group barriers

// Dynamic smem layout (floats)
#define A_OFF   0          // a_s[64][256]      16384
#define W_OFF   16384      // w_s[k=256][e=32]   8192
#define RED_OFF 24576      // red[8][32]          256
#define CS_OFF  24832      // C[64]                64
#define SMEM_FLOATS 24896
// prologue reuse: wch[256][68] at 0 (17408), xch[32][64] at 17408 (2048)

__device__ __forceinline__ float fast_tanh(float x) {
    float ax = fabsf(x);
    float e  = __expf(-2.0f * ax);
    float r  = __fdividef(1.0f - e, 1.0f + e);
    return copysignf(r, x);
}

__device__ __forceinline__ void group_barrier(int b, int tid) {
    __syncthreads();
    if (tid == 0) {
        __threadfence();
        unsigned old = atomicAdd(&g_bar[b], 1u);
        unsigned target = (old / GRP + 1u) * GRP;
        while (*((volatile unsigned*)&g_bar[b]) < target) { }
        __threadfence();
    }
    __syncthreads();
}

__global__ __launch_bounds__(NTHR, 1)
void slot_elman_kernel(const float* __restrict__ x,
                       const float* __restrict__ z,
                       const float* __restrict__ h0,
                       const float* __restrict__ Wx,
                       const float* __restrict__ Wh,
                       const float* __restrict__ bias,
                       const float* __restrict__ C,
                       float* __restrict__ d_out) {
    extern __shared__ float sm[];
    const int tid = threadIdx.x;
    const int b   = blockIdx.x / GRP;   // batch group
    const int m   = blockIdx.x % GRP;   // member (e-slice)
    const int ebase = m * NC;

    float* out_p = d_out;               // [T][B][D]
    float* h_p   = d_out + TBD;         // [T+1][B][S][D]

    // ---------------- Prologue ----------------
    // 1) wxb[t][b][:] for t in [m*32, m*32+32):  x_row @ Wx^T + bias
    {
        float* wch = sm;            // [256][68] padded
        float* xch = sm + 17408;    // [32][64]
        float pacc[32];
        #pragma unroll
        for (int i = 0; i < 32; i++) pacc[i] = 0.0f;

        for (int kt = 0; kt < 4; kt++) {
            const int k0 = kt * 64;
            __syncthreads();
            // load W chunk: wch[e][k] (padded rows of 68)
            for (int idx = tid; idx < 256 * 16; idx += NTHR) {
                int e = idx >> 4, q = idx & 15;
                float4 v = *(const float4*)(Wx + e * DD + k0 + q * 4);
                *(float4*)(wch + e * 68 + q * 4) = v;
            }
            // load x chunk: xch[i][k]
            for (int idx = tid; idx < 32 * 16; idx += NTHR) {
                int i = idx >> 4, q = idx & 15;
                int t = m * 32 + i;
                float4 v = *(const float4*)(x + (t * BB + b) * DD + k0 + q * 4);
                *(float4*)(xch + i * 64 + q * 4) = v;
            }
            __syncthreads();
            // thread owns output column e = tid
            for (int q = 0; q < 16; q++) {
                float4 wv = *(const float4*)(wch + tid * 68 + q * 4);
                #pragma unroll
                for (int i = 0; i < 32; i++) {
                    float4 xv = *(const float4*)(xch + i * 64 + q * 4);
                    pacc[i] += wv.x * xv.x + wv.y * xv.y + wv.z * xv.z + wv.w * xv.w;
                }
            }
        }
        float bb = bias[tid];
        #pragma unroll
        for (int i = 0; i < 32; i++) {
            int t = m * 32 + i;
            g_wxb[(t * BB + b) * DD + tid] = pacc[i] + bb;
        }
    }
    // 2) silu(z) for the same t-rows
    for (int idx = tid; idx < 32 * 64; idx += NTHR) {  // float4 count
        int i = idx >> 6, q = idx & 63;
        int t = m * 32 + i;
        float4 zv = *(const float4*)(z + (t * BB + b) * DD + q * 4);
        float4 sv;
        sv.x = __fdividef(zv.x, 1.0f + __expf(-zv.x));
        sv.y = __fdividef(zv.y, 1.0f + __expf(-zv.y));
        sv.z = __fdividef(zv.z, 1.0f + __expf(-zv.z));
        sv.w = __fdividef(zv.w, 1.0f + __expf(-zv.w));
        *(float4*)(g_sz + (t * BB + b) * DD + q * 4) = sv;
    }
    // 3) h[0] = h0 (member m copies 8 s-rows of its batch)
    {
        const float* src = h0 + b * (SS * DD) + (m * 8) * DD;
        float*       dst = h_p + b * (SS * DD) + (m * 8) * DD;
        for (int idx = tid; idx < 8 * 64; idx += NTHR) {
            *(float4*)(dst + idx * 4) = *(const float4*)(src + idx * 4);
        }
    }
    __syncthreads();

    // ---------------- Load resident Wh slice + C ----------------
    float* a_s = sm + A_OFF;
    float* w_s = sm + W_OFF;   // [k][e] : w_s[k*32+e] = Wh[(ebase+e)*256 + k]
    float* red = sm + RED_OFF;
    float* C_s = sm + CS_OFF;
    for (int idx = tid; idx < DD * NC; idx += NTHR) {
        int k = idx >> 5, e = idx & 31;
        w_s[idx] = Wh[(ebase + e) * DD + k];
    }
    if (tid < SS) C_s[tid] = C[tid];

    group_barrier(b, tid);  // prologue complete across the group

    // thread mapping: te = e-group (0..7, 4 cols each), ts = s-group (0..31, 2 rows each)
    const int te = tid & 7;
    const int ts = tid >> 3;
    const int s0 = ts * 2;
    const int te4 = te * 4;

    // ---------------- Main recurrence ----------------
    for (int t = 0; t < TT; t++) {
        // stage h_prev[b] into smem
        const float* hsrc = h_p + t * BSD + b * (SS * DD);
        for (int idx = tid; idx < SS * 64; idx += NTHR) {  // 4096 float4
            int s = idx >> 6, q = idx & 63;
            *(float4*)(a_s + s * DD + q * 4) = *(const float4*)(hsrc + s * DD + q * 4);
        }
        __syncthreads();

        // GEMM: acc[2 s][4 e] over K=256
        float acc00=0,acc01=0,acc02=0,acc03=0;
        float acc10=0,acc11=0,acc12=0,acc13=0;
        const float* ar0 = a_s + s0 * DD;
        const float* ar1 = a_s + (s0 + 1) * DD;
        #pragma unroll 2
        for (int k = 0; k < DD; k += 4) {
            float4 a0 = *(const float4*)(ar0 + k);
            float4 a1 = *(const float4*)(ar1 + k);
            float4 w0 = *(const float4*)(w_s + (k + 0) * NC + te4);
            float4 w1 = *(const float4*)(w_s + (k + 1) * NC + te4);
            float4 w2 = *(const float4*)(w_s + (k + 2) * NC + te4);
            float4 w3 = *(const float4*)(w_s + (k + 3) * NC + te4);
            acc00 += a0.x*w0.x; acc01 += a0.x*w0.y; acc02 += a0.x*w0.z; acc03 += a0.x*w0.w;
            acc10 += a1.x*w0.x; acc11 += a1.x*w0.y; acc12 += a1.x*w0.z; acc13 += a1.x*w0.w;
            acc00 += a0.y*w1.x; acc01 += a0.y*w1.y; acc02 += a0.y*w1.z; acc03 += a0.y*w1.w;
            acc10 += a1.y*w1.x; acc11 += a1.y*w1.y; acc12 += a1.y*w1.z; acc13 += a1.y*w1.w;
            acc00 += a0.z*w2.x; acc01 += a0.z*w2.y; acc02 += a0.z*w2.z; acc03 += a0.z*w2.w;
            acc10 += a1.z*w2.x; acc11 += a1.z*w2.y; acc12 += a1.z*w2.z; acc13 += a1.z*w2.w;
            acc00 += a0.w*w3.x; acc01 += a0.w*w3.y; acc02 += a0.w*w3.z; acc03 += a0.w*w3.w;
            acc10 += a1.w*w3.x; acc11 += a1.w*w3.y; acc12 += a1.w*w3.z; acc13 += a1.w*w3.w;
        }

        // Epilogue: tanh(acc + wxb), store h, partial C-weighted sums
        float4 wb = *(const float4*)(g_wxb + (t * BB + b) * DD + ebase + te4);
        float h00 = fast_tanh(acc00 + wb.x);
        float h01 = fast_tanh(acc01 + wb.y);
        float h02 = fast_tanh(acc02 + wb.z);
        float h03 = fast_tanh(acc03 + wb.w);
        float h10 = fast_tanh(acc10 + wb.x);
        float h11 = fast_tanh(acc11 + wb.y);
        float h12 = fast_tanh(acc12 + wb.z);
        float h13 = fast_tanh(acc13 + wb.w);

        float* hdst = h_p + (t + 1) * BSD + b * (SS * DD);
        *(float4*)(hdst + s0 * DD + ebase + te4)       = make_float4(h00, h01, h02, h03);
        *(float4*)(hdst + (s0 + 1) * DD + ebase + te4) = make_float4(h10, h11, h12, h13);

        float c0 = C_s[s0], c1 = C_s[s0 + 1];
        float p0 = h00 * c0 + h10 * c1;
        float p1 = h01 * c0 + h11 * c1;
        float p2 = h02 * c0 + h12 * c1;
        float p3 = h03 * c0 + h13 * c1;
        // reduce over the 4 ts-groups inside each warp (lanes differing in bits 3,4)
        p0 += __shfl_xor_sync(0xffffffffu, p0, 8);
        p1 += __shfl_xor_sync(0xffffffffu, p1, 8);
        p2 += __shfl_xor_sync(0xffffffffu, p2, 8);
        p3 += __shfl_xor_sync(0xffffffffu, p3, 8);
        p0 += __shfl_xor_sync(0xffffffffu, p0, 16);
        p1 += __shfl_xor_sync(0xffffffffu, p1, 16);
        p2 += __shfl_xor_sync(0xffffffffu, p2, 16);
        p3 += __shfl_xor_sync(0xffffffffu, p3, 16);
        if ((tid & 31) < 8) {
            int w = tid >> 5;
            *(float4*)(red + w * NC + te4) = make_float4(p0, p1, p2, p3);
        }
        __syncthreads();
        if (tid < NC) {
            float s = 0.0f;
            #pragma unroll
            for (int w = 0; w < 8; w++) s += red[w * NC + tid];
            float szv = g_sz[(t * BB + b) * DD + ebase + tid];
            out_p[(t * BB + b) * DD + ebase + tid] = s * szv;
        }

        group_barrier(b, tid);  // h[t+1] globally visible to the whole group
    }
}

extern "C" void kernel_launch(void* const* d_in, const int* in_sizes, int n_in,
                              void* d_out, int out_size) {
    const float* x    = (const float*)d_in[0];
    const float* z    = (const float*)d_in[1];
    const float* h0   = (const float*)d_in[2];
    const float* Wx   = (const float*)d_in[3];
    const float* Wh   = (const float*)d_in[4];
    const float* bias = (const float*)d_in[5];
    const float* C    = (const float*)d_in[6];
    float* out = (float*)d_out;

    size_t smem = SMEM_FLOATS * sizeof(float);
    cudaFuncSetAttribute(slot_elman_kernel,
                         cudaFuncAttributeMaxDynamicSharedMemorySize, (int)smem);
    slot_elman_kernel<<<NCTA, NTHR, smem>>>(x, z, h0, Wx, Wh, bias, C, out);
}

// round 4
// speedup vs baseline: 2.0125x; 2.0125x over previous
#include <cuda_runtime.h>
#include <cuda_bf16.h>
#include <cstdint>
#include <math.h>

#define TT 256
#define BB 16
#define SS 64
#define DD 256
#define SD (SS*DD)          // 16384
#define BSD (BB*SD)         // 262144
#define TBD (TT*BB*DD)      // 1048576

#define PKBUF (1024*256)    // u32 per buffer: 1024 global rows x 256 cols

__device__ float    g_wxb[TBD];
__device__ float    g_sz[TBD];
__device__ unsigned g_pack[2*PKBUF];   // [buf][row_g][e] = hi<<16|lo
__device__ unsigned g_bar[32];         // per-mslice monotonic barrier

// ---------------- helpers ----------------
__device__ __forceinline__ uint32_t smem_u32(const void* p) {
    uint32_t a;
    asm("{ .reg .u64 t; cvta.to.shared.u64 t, %1; cvt.u32.u64 %0, t; }" : "=r"(a) : "l"(p));
    return a;
}
__device__ __forceinline__ uint32_t prmt(uint32_t a, uint32_t b, uint32_t sel) {
    uint32_t d;
    asm("prmt.b32 %0, %1, %2, %3;" : "=r"(d) : "r"(a), "r"(b), "r"(sel));
    return d;
}
__device__ __forceinline__ float fast_tanh(float x) {
    float ax = fabsf(x);
    float e  = __expf(-2.0f * ax);
    float r  = __fdividef(1.0f - e, 1.0f + e);
    return copysignf(r, x);
}
__device__ __forceinline__ float silu_f(float v) {
    return __fdividef(v, 1.0f + __expf(-v));
}
__device__ __forceinline__ unsigned pack_hl(float h) {
    unsigned hb = (unsigned)__bfloat16_as_ushort(__float2bfloat16(h));
    float rem = h - __uint_as_float(hb << 16);
    return (hb << 16) | (unsigned)__bfloat16_as_ushort(__float2bfloat16(rem));
}

#define LDSM4(r0, r1, r2, r3, addr) \
    asm volatile("ldmatrix.sync.aligned.m8n8.x4.shared.b16 {%0,%1,%2,%3}, [%4];" \
        : "=r"(r0), "=r"(r1), "=r"(r2), "=r"(r3) : "r"(addr))

#define MMA16816(d, a0, a1, a2, a3, b0, b1) \
    asm volatile("mma.sync.aligned.m16n8k16.row.col.f32.bf16.bf16.f32 " \
        "{%0,%1,%2,%3}, {%4,%5,%6,%7}, {%8,%9}, {%0,%1,%2,%3};" \
        : "+f"((d)[0]), "+f"((d)[1]), "+f"((d)[2]), "+f"((d)[3]) \
        : "r"(a0), "r"(a1), "r"(a2), "r"(a3), "r"(b0), "r"(b1))

// =====================================================================
// Kernel 1 — prologue: wxb = x@Wx^T + b, silu(z), h[0] copy + pack
// =====================================================================
__global__ __launch_bounds__(256, 1)
void selman_pre(const float* __restrict__ x, const float* __restrict__ z,
                const float* __restrict__ h0, const float* __restrict__ Wx,
                const float* __restrict__ bias, float* __restrict__ d_out) {
    extern __shared__ float sm[];
    const int tid = threadIdx.x;
    const int b = blockIdx.x >> 3;
    const int m = blockIdx.x & 7;
    float* h_p = d_out + TBD;

    {   // wxb for t in [32m, 32m+32)
        float* wch = sm;           // [256][68]
        float* xch = sm + 17408;   // [32][64]
        float pacc[32];
        #pragma unroll
        for (int i = 0; i < 32; i++) pacc[i] = 0.0f;
        for (int kt = 0; kt < 4; kt++) {
            const int k0 = kt * 64;
            __syncthreads();
            for (int idx = tid; idx < 256 * 16; idx += 256) {
                int e = idx >> 4, q = idx & 15;
                *(float4*)(wch + e * 68 + q * 4) = *(const float4*)(Wx + e * DD + k0 + q * 4);
            }
            for (int idx = tid; idx < 32 * 16; idx += 256) {
                int i = idx >> 4, q = idx & 15;
                int t = m * 32 + i;
                *(float4*)(xch + i * 64 + q * 4) = *(const float4*)(x + (t * BB + b) * DD + k0 + q * 4);
            }
            __syncthreads();
            for (int q = 0; q < 16; q++) {
                float4 wv = *(const float4*)(wch + tid * 68 + q * 4);
                #pragma unroll
                for (int i = 0; i < 32; i++) {
                    float4 xv = *(const float4*)(xch + i * 64 + q * 4);
                    pacc[i] += wv.x * xv.x + wv.y * xv.y + wv.z * xv.z + wv.w * xv.w;
                }
            }
        }
        float bb = bias[tid];
        #pragma unroll
        for (int i = 0; i < 32; i++) {
            int t = m * 32 + i;
            g_wxb[(t * BB + b) * DD + tid] = pacc[i] + bb;
        }
    }
    // silu(z)
    for (int idx = tid; idx < 32 * 64; idx += 256) {
        int i = idx >> 6, q = idx & 63;
        int t = m * 32 + i;
        float4 zv = *(const float4*)(z + (t * BB + b) * DD + q * 4);
        float4 sv;
        sv.x = silu_f(zv.x); sv.y = silu_f(zv.y); sv.z = silu_f(zv.z); sv.w = silu_f(zv.w);
        *(float4*)(g_sz + (t * BB + b) * DD + q * 4) = sv;
    }
    // h[0] copy + pack (member m handles s-rows [8m, 8m+8))
    {
        const float* src = h0 + b * SD + (m * 8) * DD;
        float*       dst = h_p + b * SD + (m * 8) * DD;
        for (int idx = tid; idx < 8 * 256; idx += 256) {
            float v = src[idx];
            dst[idx] = v;
            int s = idx >> 8, e = idx & 255;
            int r_g = b * 64 + m * 8 + s;
            g_pack[r_g * 256 + e] = pack_hl(v);
        }
    }
}

// =====================================================================
// Kernel 2 — HMMA recurrence. 128 CTAs x 128 thr.
//   CTA (ms, ns): rows [32ms, 32ms+32), e-cols [64ns, 64ns+64)
//   Warps: mg = wid>>1 (m16), ng2 = wid&1 (n32).
// =====================================================================
#define A_HI 0
#define A_LO 16896              // 32*528
#define B_HI 33792
#define B_LO 67584              // B_HI + 64*528
#define SMEM_MAIN 101376

__device__ __forceinline__ void slice_barrier(int ms, int tid) {
    __syncthreads();
    if (tid == 0) {
        __threadfence();
        unsigned old = atomicAdd(&g_bar[ms], 1u);
        unsigned target = (old / 4u + 1u) * 4u;
        while (*((volatile unsigned*)&g_bar[ms]) < target) { }
        __threadfence();
    }
    __syncthreads();
}

__global__ __launch_bounds__(128, 1)
void selman_main(const float* __restrict__ Wh, float* __restrict__ d_out) {
    extern __shared__ char smc[];
    const int tid  = threadIdx.x;
    const int wid  = tid >> 5;
    const int lane = tid & 31;
    const int ms   = blockIdx.x >> 2;    // 0..31
    const int ns   = blockIdx.x & 3;     // 0..3
    float* h_p = d_out + TBD;

    // ---- resident B (weights) hi/lo, padded rows of 528B ----
    for (int idx = tid; idx < 64 * 256; idx += 128) {
        int n = idx >> 8, k = idx & 255;
        float f = Wh[(64 * ns + n) * DD + k];
        __nv_bfloat16 hb = __float2bfloat16(f);
        float rem = f - __bfloat162float(hb);
        *(__nv_bfloat16*)(smc + B_HI + n * 528 + k * 2) = hb;
        *(__nv_bfloat16*)(smc + B_LO + n * 528 + k * 2) = __float2bfloat16(rem);
    }
    __syncthreads();

    const uint32_t sb = smem_u32(smc);
    const int mg  = wid >> 1;
    const int ng2 = wid & 1;
    const int l   = lane;

    // ldmatrix lane addresses
    const uint32_t arow = (uint32_t)(16 * mg + (l & 7) + ((l >> 3) & 1) * 8);
    const uint32_t acol = (uint32_t)((l >> 4) * 8);
    const uint32_t aAH = sb + A_HI + arow * 528 + acol * 2;
    const uint32_t aAL = aAH + (A_LO - A_HI);
    const uint32_t brow = (uint32_t)(32 * ng2 + (l >> 4) * 8 + (l & 7));
    const uint32_t bk   = (uint32_t)(((l >> 3) & 1) * 8);
    const uint32_t bH0 = sb + B_HI + brow * 528 + bk * 2;
    const uint32_t bH1 = bH0 + 16 * 528;
    const uint32_t bL0 = bH0 + (B_LO - B_HI);
    const uint32_t bL1 = bH1 + (B_LO - B_HI);

    // epilogue mapping
    const int rloc = 16 * mg + (l >> 2);      // local row of d0/d1
    const int r_g  = 32 * ms + rloc;
    const int b    = ms >> 1;                 // r_g >> 6
    const int s    = r_g & 63;
    const int e00  = 64 * ns + 32 * ng2 + 2 * (l & 3);

    for (int t = 0; t < TT; t++) {
        const int pb = t & 1;

        // ---- build A hi/lo from packed exchange (L2, bypass L1) ----
        const uint4* src = (const uint4*)(g_pack + pb * PKBUF + (ms * 32) * 256);
        #pragma unroll
        for (int i = 0; i < 16; i++) {
            int idx = i * 128 + tid;
            int rr = idx >> 6, q = idx & 63;
            uint4 v = __ldcg(src + idx);
            uint32_t h0w = prmt(v.x, v.y, 0x7632u), h1w = prmt(v.z, v.w, 0x7632u);
            uint32_t l0w = prmt(v.x, v.y, 0x5410u), l1w = prmt(v.z, v.w, 0x5410u);
            *(uint2*)(smc + A_HI + rr * 528 + q * 8) = make_uint2(h0w, h1w);
            *(uint2*)(smc + A_LO + rr * 528 + q * 8) = make_uint2(l0w, l1w);
        }
        __syncthreads();

        // ---- 3-pass HMMA: acc = Ahi*Bhi + Alo*Bhi + Ahi*Blo ----
        float acc[16];
        #pragma unroll
        for (int i = 0; i < 16; i++) acc[i] = 0.0f;

        #pragma unroll 4
        for (int kc = 0; kc < 16; kc++) {
            const uint32_t ko = (uint32_t)kc * 32;
            uint32_t ah0, ah1, ah2, ah3, al0, al1, al2, al3;
            uint32_t bh[8], bl[8];
            LDSM4(ah0, ah1, ah2, ah3, aAH + ko);
            LDSM4(al0, al1, al2, al3, aAL + ko);
            LDSM4(bh[0], bh[1], bh[2], bh[3], bH0 + ko);
            LDSM4(bh[4], bh[5], bh[6], bh[7], bH1 + ko);
            LDSM4(bl[0], bl[1], bl[2], bl[3], bL0 + ko);
            LDSM4(bl[4], bl[5], bl[6], bl[7], bL1 + ko);
            #pragma unroll
            for (int j = 0; j < 4; j++) {
                MMA16816(acc + 4 * j, ah0, ah1, ah2, ah3, bh[2 * j], bh[2 * j + 1]);
                MMA16816(acc + 4 * j, al0, al1, al2, al3, bh[2 * j], bh[2 * j + 1]);
                MMA16816(acc + 4 * j, ah0, ah1, ah2, ah3, bl[2 * j], bl[2 * j + 1]);
            }
        }

        // ---- epilogue: tanh(acc + wxb), store fp32 h + packed ----
        const float* wp  = g_wxb + (t * BB + b) * DD;
        float*       hd0 = h_p + (t + 1) * BSD + b * SD + s * DD;
        float*       hd1 = hd0 + 8 * DD;
        unsigned*    pk  = g_pack + (pb ^ 1) * PKBUF + r_g * 256;
        #pragma unroll
        for (int j = 0; j < 4; j++) {
            int e = e00 + 8 * j;
            float2 wb = *(const float2*)(wp + e);
            float v0 = fast_tanh(acc[4 * j + 0] + wb.x);
            float v1 = fast_tanh(acc[4 * j + 1] + wb.y);
            float v2 = fast_tanh(acc[4 * j + 2] + wb.x);
            float v3 = fast_tanh(acc[4 * j + 3] + wb.y);
            *(float2*)(hd0 + e) = make_float2(v0, v1);
            *(float2*)(hd1 + e) = make_float2(v2, v3);
            *(uint2*)(pk + e)            = make_uint2(pack_hl(v0), pack_hl(v1));
            *(uint2*)(pk + 8 * 256 + e)  = make_uint2(pack_hl(v2), pack_hl(v3));
        }

        slice_barrier(ms, tid);
    }
}

// =====================================================================
// Kernel 3 — out[t][b][e] = (sum_s h[t+1][b][s][e] * C[s]) * silu(z)
// =====================================================================
__global__ __launch_bounds__(256, 1)
void selman_out(const float* __restrict__ C, float* __restrict__ d_out) {
    __shared__ float Cs[64];
    const int tid = threadIdx.x;
    const int t = blockIdx.x >> 4;
    const int b = blockIdx.x & 15;
    if (tid < 64) Cs[tid] = C[tid];
    __syncthreads();
    const float* hp = d_out + TBD + (t + 1) * BSD + b * SD;
    float acc = 0.0f;
    #pragma unroll 8
    for (int s = 0; s < 64; s++) acc += hp[s * DD + tid] * Cs[s];
    int o = (t * BB + b) * DD + tid;
    d_out[o] = acc * g_sz[o];
}

extern "C" void kernel_launch(void* const* d_in, const int* in_sizes, int n_in,
                              void* d_out, int out_size) {
    const float* x    = (const float*)d_in[0];
    const float* z    = (const float*)d_in[1];
    const float* h0   = (const float*)d_in[2];
    const float* Wx   = (const float*)d_in[3];
    const float* Wh   = (const float*)d_in[4];
    const float* bias = (const float*)d_in[5];
    const float* C    = (const float*)d_in[6];
    float* out = (float*)d_out;

    size_t smem_pre = 19456 * sizeof(float);
    cudaFuncSetAttribute(selman_pre, cudaFuncAttributeMaxDynamicSharedMemorySize, (int)smem_pre);
    cudaFuncSetAttribute(selman_main, cudaFuncAttributeMaxDynamicSharedMemorySize, SMEM_MAIN);

    selman_pre<<<128, 256, smem_pre>>>(x, z, h0, Wx, bias, out);
    selman_main<<<128, 128, SMEM_MAIN>>>(Wh, out);
    selman_out<<<TT * BB, 256>>>(C, out);
}

// round 5
// speedup vs baseline: 2.9174x; 1.4496x over previous
#include <cuda_runtime.h>
#include <cuda_bf16.h>
#include <cstdint>
#include <math.h>

#define TT 256
#define BB 16
#define SS 64
#define DD 256
#define SD (SS*DD)          // 16384
#define BSD (BB*SD)         // 262144
#define TBD (TT*BB*DD)      // 1048576

#define PKBUF (1024*256)    // u32 per buffer: 1024 global rows x 256 cols

__device__ float    g_wxb[TBD];
__device__ unsigned g_pack[2*PKBUF];   // [buf][row_g][e] = hi<<16|lo

// ---------------- helpers ----------------
__device__ __forceinline__ uint32_t smem_u32(const void* p) {
    uint32_t a;
    asm("{ .reg .u64 t; cvta.to.shared.u64 t, %1; cvt.u32.u64 %0, t; }" : "=r"(a) : "l"(p));
    return a;
}
__device__ __forceinline__ uint32_t prmt(uint32_t a, uint32_t b, uint32_t sel) {
    uint32_t d;
    asm("prmt.b32 %0, %1, %2, %3;" : "=r"(d) : "r"(a), "r"(b), "r"(sel));
    return d;
}
__device__ __forceinline__ float fast_tanh(float x) {
    float ax = fabsf(x);
    float e  = __expf(-2.0f * ax);
    float r  = __fdividef(1.0f - e, 1.0f + e);
    return copysignf(r, x);
}
__device__ __forceinline__ float silu_f(float v) {
    return __fdividef(v, 1.0f + __expf(-v));
}
__device__ __forceinline__ unsigned pack_hl(float h) {
    unsigned hb = (unsigned)__bfloat16_as_ushort(__float2bfloat16(h));
    float rem = h - __uint_as_float(hb << 16);
    return (hb << 16) | (unsigned)__bfloat16_as_ushort(__float2bfloat16(rem));
}

#define LDSM4(r0, r1, r2, r3, addr) \
    asm volatile("ldmatrix.sync.aligned.m8n8.x4.shared.b16 {%0,%1,%2,%3}, [%4];" \
        : "=r"(r0), "=r"(r1), "=r"(r2), "=r"(r3) : "r"(addr))

#define MMA16816(d, a0, a1, a2, a3, b0, b1) \
    asm volatile("mma.sync.aligned.m16n8k16.row.col.f32.bf16.bf16.f32 " \
        "{%0,%1,%2,%3}, {%4,%5,%6,%7}, {%8,%9}, {%0,%1,%2,%3};" \
        : "+f"((d)[0]), "+f"((d)[1]), "+f"((d)[2]), "+f"((d)[3]) \
        : "r"(a0), "r"(a1), "r"(a2), "r"(a3), "r"(b0), "r"(b1))

#define CLUSTER_ARRIVE() asm volatile("barrier.cluster.arrive.aligned;" ::: "memory")
#define CLUSTER_WAIT()   asm volatile("barrier.cluster.wait.aligned;" ::: "memory")

// =====================================================================
// Kernel 1 — prologue: wxb = x@Wx^T + b, h[0] copy + pack
// =====================================================================
__global__ __launch_bounds__(256, 1)
void selman_pre(const float* __restrict__ x, const float* __restrict__ z,
                const float* __restrict__ h0, const float* __restrict__ Wx,
                const float* __restrict__ bias, float* __restrict__ d_out) {
    extern __shared__ float sm[];
    const int tid = threadIdx.x;
    const int b = blockIdx.x >> 3;
    const int m = blockIdx.x & 7;
    float* h_p = d_out + TBD;

    {   // wxb for t in [32m, 32m+32)
        float* wch = sm;           // [256][68]
        float* xch = sm + 17408;   // [32][64]
        float pacc[32];
        #pragma unroll
        for (int i = 0; i < 32; i++) pacc[i] = 0.0f;
        for (int kt = 0; kt < 4; kt++) {
            const int k0 = kt * 64;
            __syncthreads();
            for (int idx = tid; idx < 256 * 16; idx += 256) {
                int e = idx >> 4, q = idx & 15;
                *(float4*)(wch + e * 68 + q * 4) = *(const float4*)(Wx + e * DD + k0 + q * 4);
            }
            for (int idx = tid; idx < 32 * 16; idx += 256) {
                int i = idx >> 4, q = idx & 15;
                int t = m * 32 + i;
                *(float4*)(xch + i * 64 + q * 4) = *(const float4*)(x + (t * BB + b) * DD + k0 + q * 4);
            }
            __syncthreads();
            for (int q = 0; q < 16; q++) {
                float4 wv = *(const float4*)(wch + tid * 68 + q * 4);
                #pragma unroll
                for (int i = 0; i < 32; i++) {
                    float4 xv = *(const float4*)(xch + i * 64 + q * 4);
                    pacc[i] += wv.x * xv.x + wv.y * xv.y + wv.z * xv.z + wv.w * xv.w;
                }
            }
        }
        float bb = bias[tid];
        #pragma unroll
        for (int i = 0; i < 32; i++) {
            int t = m * 32 + i;
            g_wxb[(t * BB + b) * DD + tid] = pacc[i] + bb;
        }
    }
    // h[0] copy + pack (member m handles s-rows [8m, 8m+8))
    {
        const float* src = h0 + b * SD + (m * 8) * DD;
        float*       dst = h_p + b * SD + (m * 8) * DD;
        for (int idx = tid; idx < 8 * 256; idx += 256) {
            float v = src[idx];
            dst[idx] = v;
            int s = idx >> 8, e = idx & 255;
            int r_g = b * 64 + m * 8 + s;
            g_pack[r_g * 256 + e] = pack_hl(v);
        }
    }
}

// =====================================================================
// Kernel 2 — HMMA recurrence. 128 CTAs x 256 thr, clusters of 4.
//   CTA (ms, ns): rows [32ms, 32ms+32), e-cols [64ns, 64ns+64)
//   8 warps: mg = wid>>2 (m16), ng = wid&3 (n16). B-hi in registers.
// =====================================================================
#define A_HI 0
#define A_LO 16896              // 32*528
#define B_HI 33792
#define B_LO 67584              // B_HI + 64*528
#define SMEM_MAIN 101376

__global__ __launch_bounds__(256, 1) __cluster_dims__(4, 1, 1)
void selman_main(const float* __restrict__ Wh, float* __restrict__ d_out) {
    extern __shared__ char smc[];
    const int tid  = threadIdx.x;
    const int wid  = tid >> 5;
    const int lane = tid & 31;
    const int ms   = blockIdx.x >> 2;    // 0..31
    const int ns   = blockIdx.x & 3;     // 0..3 (== cluster rank)
    float* h_p = d_out + TBD;

    // ---- resident B (weights) hi/lo in smem, padded rows of 528B ----
    for (int idx = tid; idx < 64 * 256; idx += 256) {
        int n = idx >> 8, k = idx & 255;
        float f = Wh[(64 * ns + n) * DD + k];
        __nv_bfloat16 hb = __float2bfloat16(f);
        float rem = f - __bfloat162float(hb);
        *(__nv_bfloat16*)(smc + B_HI + n * 528 + k * 2) = hb;
        *(__nv_bfloat16*)(smc + B_LO + n * 528 + k * 2) = __float2bfloat16(rem);
    }
    __syncthreads();

    const uint32_t sb = smem_u32(smc);
    const int mg = wid >> 2;          // 0..1 : m16
    const int ng = wid & 3;           // 0..3 : n16
    const int l  = lane;

    // ldmatrix lane addresses
    const uint32_t arow = (uint32_t)(16 * mg + (l & 7) + ((l >> 3) & 1) * 8);
    const uint32_t acol = (uint32_t)((l >> 4) * 8);
    const uint32_t aAH = sb + A_HI + arow * 528 + acol * 2;
    const uint32_t aAL = aAH + (A_LO - A_HI);
    const uint32_t brow = (uint32_t)(16 * ng + (l >> 4) * 8 + (l & 7));
    const uint32_t bk   = (uint32_t)(((l >> 3) & 1) * 8);
    const uint32_t bH = sb + B_HI + brow * 528 + bk * 2;
    const uint32_t bL = bH + (B_LO - B_HI);

    // ---- preload B-hi into registers (once) ----
    uint32_t bhr[16][4];
    #pragma unroll
    for (int kc = 0; kc < 16; kc++) {
        LDSM4(bhr[kc][0], bhr[kc][1], bhr[kc][2], bhr[kc][3], bH + (uint32_t)kc * 32);
    }

    // epilogue mapping
    const int rloc = 16 * mg + (l >> 2);      // local row of d0/d1
    const int r_g  = 32 * ms + rloc;
    const int b    = ms >> 1;
    const int s    = r_g & 63;
    const int e00  = 64 * ns + 16 * ng + 2 * (l & 3);

    for (int t = 0; t < TT; t++) {
        const int pb = t & 1;

        // ---- build A hi/lo from packed exchange (L2, bypass L1) ----
        const uint4* src = (const uint4*)(g_pack + pb * PKBUF + (ms * 32) * 256);
        #pragma unroll
        for (int i = 0; i < 8; i++) {
            int idx = i * 256 + tid;
            int rr = idx >> 6, q = idx & 63;
            uint4 v = __ldcg(src + idx);
            uint32_t h0w = prmt(v.x, v.y, 0x7632u), h1w = prmt(v.z, v.w, 0x7632u);
            uint32_t l0w = prmt(v.x, v.y, 0x5410u), l1w = prmt(v.z, v.w, 0x5410u);
            *(uint2*)(smc + A_HI + rr * 528 + q * 8) = make_uint2(h0w, h1w);
            *(uint2*)(smc + A_LO + rr * 528 + q * 8) = make_uint2(l0w, l1w);
        }
        __syncthreads();

        // ---- 3-pass HMMA: acc = Ahi*Bhi + Alo*Bhi + Ahi*Blo ----
        float acc[8];
        #pragma unroll
        for (int i = 0; i < 8; i++) acc[i] = 0.0f;

        #pragma unroll
        for (int kc = 0; kc < 16; kc++) {
            const uint32_t ko = (uint32_t)kc * 32;
            uint32_t ah0, ah1, ah2, ah3, al0, al1, al2, al3;
            uint32_t bl0, bl1, bl2, bl3;
            LDSM4(ah0, ah1, ah2, ah3, aAH + ko);
            LDSM4(al0, al1, al2, al3, aAL + ko);
            LDSM4(bl0, bl1, bl2, bl3, bL + ko);
            MMA16816(acc + 0, ah0, ah1, ah2, ah3, bhr[kc][0], bhr[kc][1]);
            MMA16816(acc + 4, ah0, ah1, ah2, ah3, bhr[kc][2], bhr[kc][3]);
            MMA16816(acc + 0, al0, al1, al2, al3, bhr[kc][0], bhr[kc][1]);
            MMA16816(acc + 4, al0, al1, al2, al3, bhr[kc][2], bhr[kc][3]);
            MMA16816(acc + 0, ah0, ah1, ah2, ah3, bl0, bl1);
            MMA16816(acc + 4, ah0, ah1, ah2, ah3, bl2, bl3);
        }

        // ---- epilogue: tanh(acc + wxb), store fp32 h + packed ----
        const float* wp  = g_wxb + (t * BB + b) * DD;
        float*       hd0 = h_p + (t + 1) * BSD + b * SD + s * DD;
        float*       hd1 = hd0 + 8 * DD;
        unsigned*    pk  = g_pack + (pb ^ 1) * PKBUF + r_g * 256;
        #pragma unroll
        for (int j = 0; j < 2; j++) {
            int e = e00 + 8 * j;
            float2 wb = *(const float2*)(wp + e);
            float v0 = fast_tanh(acc[4 * j + 0] + wb.x);
            float v1 = fast_tanh(acc[4 * j + 1] + wb.y);
            float v2 = fast_tanh(acc[4 * j + 2] + wb.x);
            float v3 = fast_tanh(acc[4 * j + 3] + wb.y);
            *(float2*)(hd0 + e) = make_float2(v0, v1);
            *(float2*)(hd1 + e) = make_float2(v2, v3);
            *(uint2*)(pk + e)            = make_uint2(pack_hl(v0), pack_hl(v1));
            *(uint2*)(pk + 8 * 256 + e)  = make_uint2(pack_hl(v2), pack_hl(v3));
        }

        // cluster-wide barrier: release epilogue stores, acquire for next read
        CLUSTER_ARRIVE();
        CLUSTER_WAIT();
    }
}

// =====================================================================
// Kernel 3 — out[t][b][e] = (sum_s h[t+1][b][s][e] * C[s]) * silu(z)
// =====================================================================
__global__ __launch_bounds__(256, 1)
void selman_out(const float* __restrict__ C, const float* __restrict__ z,
                float* __restrict__ d_out) {
    __shared__ float Cs[64];
    const int tid = threadIdx.x;
    const int t = blockIdx.x >> 4;
    const int b = blockIdx.x & 15;
    if (tid < 64) Cs[tid] = C[tid];
    __syncthreads();
    const float* hp = d_out + TBD + (t + 1) * BSD + b * SD;
    float acc = 0.0f;
    #pragma unroll 8
    for (int s = 0; s < 64; s++) acc += hp[s * DD + tid] * Cs[s];
    int o = (t * BB + b) * DD + tid;
    d_out[o] = acc * silu_f(z[o]);
}

extern "C" void kernel_launch(void* const* d_in, const int* in_sizes, int n_in,
                              void* d_out, int out_size) {
    const float* x    = (const float*)d_in[0];
    const float* z    = (const float*)d_in[1];
    const float* h0   = (const float*)d_in[2];
    const float* Wx   = (const float*)d_in[3];
    const float* Wh   = (const float*)d_in[4];
    const float* bias = (const float*)d_in[5];
    const float* C    = (const float*)d_in[6];
    float* out = (float*)d_out;

    size_t smem_pre = 19456 * sizeof(float);
    cudaFuncSetAttribute(selman_pre, cudaFuncAttributeMaxDynamicSharedMemorySize, (int)smem_pre);
    cudaFuncSetAttribute(selman_main, cudaFuncAttributeMaxDynamicSharedMemorySize, SMEM_MAIN);

    selman_pre<<<128, 256, smem_pre>>>(x, z, h0, Wx, bias, out);
    selman_main<<<128, 256, SMEM_MAIN>>>(Wh, out);
    selman_out<<<TT * BB, 256>>>(C, z, out);
}

// round 6
// speedup vs baseline: 4.3827x; 1.5023x over previous
#include <cuda_runtime.h>
#include <cuda_bf16.h>
#include <cuda_fp16.h>
#include <cstdint>
#include <math.h>

#define TT 256
#define BB 16
#define SS 64
#define DD 256
#define SD (SS*DD)          // 16384
#define BSD (BB*SD)         // 262144
#define TBD (TT*BB*DD)      // 1048576

__device__ float g_wxb[TBD];

// ---------------- helpers ----------------
__device__ __forceinline__ uint32_t smem_u32(const void* p) {
    uint32_t a;
    asm("{ .reg .u64 t; cvta.to.shared.u64 t, %1; cvt.u32.u64 %0, t; }" : "=r"(a) : "l"(p));
    return a;
}
__device__ __forceinline__ float fast_tanh(float x) {
    float ax = fabsf(x);
    float e  = __expf(-2.0f * ax);
    float r  = __fdividef(1.0f - e, 1.0f + e);
    return copysignf(r, x);
}
__device__ __forceinline__ float silu_f(float v) {
    return __fdividef(v, 1.0f + __expf(-v));
}

#define LDSM4(r0, r1, r2, r3, addr) \
    asm volatile("ldmatrix.sync.aligned.m8n8.x4.shared.b16 {%0,%1,%2,%3}, [%4];" \
        : "=r"(r0), "=r"(r1), "=r"(r2), "=r"(r3) : "r"(addr))

#define MMAF16(d, a0, a1, a2, a3, b0, b1) \
    asm volatile("mma.sync.aligned.m16n8k16.row.col.f32.f16.f16.f32 " \
        "{%0,%1,%2,%3}, {%4,%5,%6,%7}, {%8,%9}, {%0,%1,%2,%3};" \
        : "+f"((d)[0]), "+f"((d)[1]), "+f"((d)[2]), "+f"((d)[3]) \
        : "r"(a0), "r"(a1), "r"(a2), "r"(a3), "r"(b0), "r"(b1))

#define CLUSTER_ARRIVE() asm volatile("barrier.cluster.arrive.aligned;" ::: "memory")
#define CLUSTER_WAIT()   asm volatile("barrier.cluster.wait.aligned;" ::: "memory")
#define STS_CLUSTER(addr, val) \
    asm volatile("st.shared::cluster.u32 [%0], %1;" :: "r"(addr), "r"(val) : "memory")

// =====================================================================
// Kernel 1 — prologue: wxb = x@Wx^T + b, h[0] copy
// =====================================================================
__global__ __launch_bounds__(256, 1)
void selman_pre(const float* __restrict__ x, const float* __restrict__ h0,
                const float* __restrict__ Wx, const float* __restrict__ bias,
                float* __restrict__ d_out) {
    extern __shared__ float sm[];
    const int tid = threadIdx.x;
    const int b = blockIdx.x >> 3;
    const int m = blockIdx.x & 7;
    float* h_p = d_out + TBD;

    {   // wxb for t in [32m, 32m+32)
        float* wch = sm;           // [256][68]
        float* xch = sm + 17408;   // [32][64]
        float pacc[32];
        #pragma unroll
        for (int i = 0; i < 32; i++) pacc[i] = 0.0f;
        for (int kt = 0; kt < 4; kt++) {
            const int k0 = kt * 64;
            __syncthreads();
            for (int idx = tid; idx < 256 * 16; idx += 256) {
                int e = idx >> 4, q = idx & 15;
                *(float4*)(wch + e * 68 + q * 4) = *(const float4*)(Wx + e * DD + k0 + q * 4);
            }
            for (int idx = tid; idx < 32 * 16; idx += 256) {
                int i = idx >> 4, q = idx & 15;
                int t = m * 32 + i;
                *(float4*)(xch + i * 64 + q * 4) = *(const float4*)(x + (t * BB + b) * DD + k0 + q * 4);
            }
            __syncthreads();
            for (int q = 0; q < 16; q++) {
                float4 wv = *(const float4*)(wch + tid * 68 + q * 4);
                #pragma unroll
                for (int i = 0; i < 32; i++) {
                    float4 xv = *(const float4*)(xch + i * 64 + q * 4);
                    pacc[i] += wv.x * xv.x + wv.y * xv.y + wv.z * xv.z + wv.w * xv.w;
                }
            }
        }
        float bb = bias[tid];
        #pragma unroll
        for (int i = 0; i < 32; i++) {
            int t = m * 32 + i;
            g_wxb[(t * BB + b) * DD + tid] = pacc[i] + bb;
        }
    }
    // h[0] copy (member m handles s-rows [8m, 8m+8))
    {
        const float* src = h0 + b * SD + (m * 8) * DD;
        float*       dst = h_p + b * SD + (m * 8) * DD;
        for (int idx = tid; idx < 8 * 64; idx += 256) {
            *(float4*)(dst + idx * 4) = *(const float4*)(src + idx * 4);
        }
    }
}

// =====================================================================
// Kernel 2 — fp16 2-pass HMMA recurrence. 128 CTAs x 256 thr, cluster 2.
//   CTA: rg = blockIdx>>1 (b = rg>>2, s-rows [16*(rg&3), +16)),
//        rank = blockIdx&1 -> e-cols [128*rank, +128).
//   8 warps, each n16. A (h) hi/lo fp16 double-buffered in SMEM,
//   exchanged with the peer CTA via DSMEM stores. B (Wh fp16) in regs.
// =====================================================================
// SMEM: A [2 bufs][2 hi/lo][16 rows][528 B]  = 33792
//       B [128 n][528 B]                      = 67584  at 33792
#define A_OFF 0
#define A_BUFSZ 16896
#define A_LOSZ  8448
#define B_OFF 33792
#define SMEM_MAIN 101376

__global__ __launch_bounds__(256, 1) __cluster_dims__(2, 1, 1)
void selman_main(const float* __restrict__ Wh, const float* __restrict__ h0,
                 float* __restrict__ d_out) {
    extern __shared__ char smc[];
    const int tid  = threadIdx.x;
    const int wid  = tid >> 5;
    const int l    = tid & 31;
    const int rg   = blockIdx.x >> 1;     // 0..63
    const int rank = blockIdx.x & 1;      // e-half
    const int b    = rg >> 2;
    const int sbase = (rg & 3) * 16;
    float* h_p = d_out + TBD;

    // ---- B (Wh fp16) into padded SMEM ----
    for (int idx = tid; idx < 128 * 256; idx += 256) {
        int n = idx >> 8, k = idx & 255;
        *(__half*)(smc + B_OFF + n * 528 + k * 2) =
            __float2half(Wh[(128 * rank + n) * DD + k]);
    }
    // ---- A buf0 init from h0 (full 256 k-cols of our 16 rows) ----
    for (int idx = tid; idx < 16 * 256; idx += 256) {
        int row = idx >> 8, k = idx & 255;
        float v = h0[b * SD + (sbase + row) * DD + k];
        __half hi = __float2half(v);
        __half lo = __float2half(v - __half2float(hi));
        *(__half*)(smc + A_OFF + row * 528 + k * 2)          = hi;
        *(__half*)(smc + A_OFF + A_LOSZ + row * 528 + k * 2) = lo;
    }
    __syncthreads();

    const uint32_t sb = smem_u32(smc);

    // ---- preload B into registers (n16 per warp, 16 k-chunks) ----
    const uint32_t brow = (uint32_t)(16 * wid + ((l >> 4) << 3) + (l & 7));
    const uint32_t bk   = (uint32_t)(((l >> 3) & 1) << 3);
    const uint32_t bAddr = sb + B_OFF + brow * 528 + bk * 2;
    uint32_t br[16][4];
    #pragma unroll
    for (int kc = 0; kc < 16; kc++)
        LDSM4(br[kc][0], br[kc][1], br[kc][2], br[kc][3], bAddr + (uint32_t)kc * 32);

    // ---- A ldmatrix lane address (m16) ----
    const uint32_t arow = (uint32_t)((l & 7) + (((l >> 3) & 1) << 3));
    const uint32_t acol = (uint32_t)((l >> 4) << 3);
    const uint32_t aBase = sb + A_OFF + arow * 528 + acol * 2;

    // ---- peer A base via mapa ----
    uint32_t peerA;
    asm("mapa.shared::cluster.u32 %0, %1, %2;"
        : "=r"(peerA) : "r"(sb + A_OFF), "r"(rank ^ 1));

    // ---- epilogue mapping ----
    const int row0  = l >> 2;               // rows row0, row0+8
    const int cloc  = 16 * wid + 2 * (l & 3);   // local e (j=0); j=1 adds 8
    const int eg0   = 128 * rank + cloc;

    for (int t = 0; t < TT; t++) {
        const int pb = t & 1;

        // prefetch wxb (hidden under MMA)
        const float* wp = g_wxb + (t * BB + b) * DD + eg0;
        float2 w0 = __ldg((const float2*)(wp));
        float2 w1 = __ldg((const float2*)(wp + 8));

        const uint32_t aH = aBase + (uint32_t)pb * A_BUFSZ;
        const uint32_t aL = aH + A_LOSZ;
        float acc[8];
        #pragma unroll
        for (int i = 0; i < 8; i++) acc[i] = 0.0f;

        #pragma unroll
        for (int kc = 0; kc < 16; kc++) {
            const uint32_t ko = (uint32_t)kc * 32;
            uint32_t ah0, ah1, ah2, ah3, al0, al1, al2, al3;
            LDSM4(ah0, ah1, ah2, ah3, aH + ko);
            LDSM4(al0, al1, al2, al3, aL + ko);
            MMAF16(acc + 0, ah0, ah1, ah2, ah3, br[kc][0], br[kc][1]);
            MMAF16(acc + 4, ah0, ah1, ah2, ah3, br[kc][2], br[kc][3]);
            MMAF16(acc + 0, al0, al1, al2, al3, br[kc][0], br[kc][1]);
            MMAF16(acc + 4, al0, al1, al2, al3, br[kc][2], br[kc][3]);
        }

        // ---- epilogue: tanh, STG h fp32, write A(t+1) local + peer ----
        const uint32_t nbOff = (uint32_t)(pb ^ 1) * A_BUFSZ;
        float* hd = h_p + (t + 1) * BSD + b * SD + sbase * DD;
        #pragma unroll
        for (int j = 0; j < 2; j++) {
            float2 wv = j ? w1 : w0;
            float v00 = fast_tanh(acc[4 * j + 0] + wv.x);
            float v01 = fast_tanh(acc[4 * j + 1] + wv.y);
            float v10 = fast_tanh(acc[4 * j + 2] + wv.x);
            float v11 = fast_tanh(acc[4 * j + 3] + wv.y);
            int eg = eg0 + 8 * j;
            *(float2*)(hd + row0 * DD + eg)       = make_float2(v00, v01);
            *(float2*)(hd + (row0 + 8) * DD + eg) = make_float2(v10, v11);

            __half2 H0 = __floats2half2_rn(v00, v01);
            __half2 H1 = __floats2half2_rn(v10, v11);
            float2 f0 = __half22float2(H0);
            float2 f1 = __half22float2(H1);
            __half2 L0 = __floats2half2_rn(v00 - f0.x, v01 - f0.y);
            __half2 L1 = __floats2half2_rn(v10 - f1.x, v11 - f1.y);
            uint32_t uH0 = *(uint32_t*)&H0, uH1 = *(uint32_t*)&H1;
            uint32_t uL0 = *(uint32_t*)&L0, uL1 = *(uint32_t*)&L1;

            uint32_t o0 = nbOff + (uint32_t)(row0 * 528 + eg * 2);
            uint32_t o1 = nbOff + (uint32_t)((row0 + 8) * 528 + eg * 2);
            // local
            *(uint32_t*)(smc + A_OFF + o0)          = uH0;
            *(uint32_t*)(smc + A_OFF + o1)          = uH1;
            *(uint32_t*)(smc + A_OFF + o0 + A_LOSZ) = uL0;
            *(uint32_t*)(smc + A_OFF + o1 + A_LOSZ) = uL1;
            // peer (DSMEM)
            STS_CLUSTER(peerA + o0,          uH0);
            STS_CLUSTER(peerA + o1,          uH1);
            STS_CLUSTER(peerA + o0 + A_LOSZ, uL0);
            STS_CLUSTER(peerA + o1 + A_LOSZ, uL1);
        }

        // release our DSMEM/SMEM writes, acquire peer's, before next read
        CLUSTER_ARRIVE();
        CLUSTER_WAIT();
    }
}

// =====================================================================
// Kernel 3 — out[t][b][e] = (sum_s h[t+1][b][s][e] * C[s]) * silu(z)
// =====================================================================
__global__ __launch_bounds__(256, 1)
void selman_out(const float* __restrict__ C, const float* __restrict__ z,
                float* __restrict__ d_out) {
    __shared__ float Cs[64];
    const int tid = threadIdx.x;
    const int t = blockIdx.x >> 4;
    const int b = blockIdx.x & 15;
    if (tid < 64) Cs[tid] = C[tid];
    __syncthreads();
    const float* hp = d_out + TBD + (t + 1) * BSD + b * SD;
    float acc = 0.0f;
    #pragma unroll 8
    for (int s = 0; s < 64; s++) acc += hp[s * DD + tid] * Cs[s];
    int o = (t * BB + b) * DD + tid;
    d_out[o] = acc * silu_f(z[o]);
}

extern "C" void kernel_launch(void* const* d_in, const int* in_sizes, int n_in,
                              void* d_out, int out_size) {
    const float* x    = (const float*)d_in[0];
    const float* z    = (const float*)d_in[1];
    const float* h0   = (const float*)d_in[2];
    const float* Wx   = (const float*)d_in[3];
    const float* Wh   = (const float*)d_in[4];
    const float* bias = (const float*)d_in[5];
    const float* C    = (const float*)d_in[6];
    float* out = (float*)d_out;

    size_t smem_pre = 19456 * sizeof(float);
    cudaFuncSetAttribute(selman_pre, cudaFuncAttributeMaxDynamicSharedMemorySize, (int)smem_pre);
    cudaFuncSetAttribute(selman_main, cudaFuncAttributeMaxDynamicSharedMemorySize, SMEM_MAIN);

    selman_pre<<<128, 256, smem_pre>>>(x, h0, Wx, bias, out);
    selman_main<<<128, 256, SMEM_MAIN>>>(Wh, h0, out);
    selman_out<<<TT * BB, 256>>>(C, z, out);
}

// round 7
// speedup vs baseline: 4.6248x; 1.0552x over previous
#include <cuda_runtime.h>
#include <cuda_bf16.h>
#include <cuda_fp16.h>
#include <cstdint>
#include <math.h>

#define TT 256
#define BB 16
#define SS 64
#define DD 256
#define SD (SS*DD)          // 16384
#define BSD (BB*SD)         // 262144
#define TBD (TT*BB*DD)      // 1048576

__device__ float g_wxb[TBD];
__device__ float g_red[TT*BB*4*DD];   // partial C-reductions [t][b][sg][e]

// ---------------- helpers ----------------
__device__ __forceinline__ uint32_t smem_u32(const void* p) {
    uint32_t a;
    asm("{ .reg .u64 t; cvta.to.shared.u64 t, %1; cvt.u32.u64 %0, t; }" : "=r"(a) : "l"(p));
    return a;
}
__device__ __forceinline__ float fast_tanh(float x) {
    float ax = fabsf(x);
    float e  = __expf(-2.0f * ax);
    float r  = __fdividef(1.0f - e, 1.0f + e);
    return copysignf(r, x);
}
__device__ __forceinline__ float silu_f(float v) {
    return __fdividef(v, 1.0f + __expf(-v));
}

#define LDSM4(r0, r1, r2, r3, addr) \
    asm volatile("ldmatrix.sync.aligned.m8n8.x4.shared.b16 {%0,%1,%2,%3}, [%4];" \
        : "=r"(r0), "=r"(r1), "=r"(r2), "=r"(r3) : "r"(addr))

#define MMAF16(d, a0, a1, a2, a3, b0, b1) \
    asm volatile("mma.sync.aligned.m16n8k16.row.col.f32.f16.f16.f32 " \
        "{%0,%1,%2,%3}, {%4,%5,%6,%7}, {%8,%9}, {%0,%1,%2,%3};" \
        : "+f"((d)[0]), "+f"((d)[1]), "+f"((d)[2]), "+f"((d)[3]) \
        : "r"(a0), "r"(a1), "r"(a2), "r"(a3), "r"(b0), "r"(b1))

#define CLUSTER_ARRIVE() asm volatile("barrier.cluster.arrive.aligned;" ::: "memory")
#define CLUSTER_WAIT()   asm volatile("barrier.cluster.wait.aligned;" ::: "memory")
#define STS_CLUSTER(addr, val) \
    asm volatile("st.shared::cluster.u32 [%0], %1;" :: "r"(addr), "r"(val) : "memory")

// =====================================================================
// Kernel 1 — prologue: wxb = x@Wx^T + b, h[0] copy  (unchanged, proven)
// =====================================================================
__global__ __launch_bounds__(256, 1)
void selman_pre(const float* __restrict__ x, const float* __restrict__ h0,
                const float* __restrict__ Wx, const float* __restrict__ bias,
                float* __restrict__ d_out) {
    extern __shared__ float sm[];
    const int tid = threadIdx.x;
    const int b = blockIdx.x >> 3;
    const int m = blockIdx.x & 7;
    float* h_p = d_out + TBD;

    {   // wxb for t in [32m, 32m+32)
        float* wch = sm;           // [256][68]
        float* xch = sm + 17408;   // [32][64]
        float pacc[32];
        #pragma unroll
        for (int i = 0; i < 32; i++) pacc[i] = 0.0f;
        for (int kt = 0; kt < 4; kt++) {
            const int k0 = kt * 64;
            __syncthreads();
            for (int idx = tid; idx < 256 * 16; idx += 256) {
                int e = idx >> 4, q = idx & 15;
                *(float4*)(wch + e * 68 + q * 4) = *(const float4*)(Wx + e * DD + k0 + q * 4);
            }
            for (int idx = tid; idx < 32 * 16; idx += 256) {
                int i = idx >> 4, q = idx & 15;
                int t = m * 32 + i;
                *(float4*)(xch + i * 64 + q * 4) = *(const float4*)(x + (t * BB + b) * DD + k0 + q * 4);
            }
            __syncthreads();
            for (int q = 0; q < 16; q++) {
                float4 wv = *(const float4*)(wch + tid * 68 + q * 4);
                #pragma unroll
                for (int i = 0; i < 32; i++) {
                    float4 xv = *(const float4*)(xch + i * 64 + q * 4);
                    pacc[i] += wv.x * xv.x + wv.y * xv.y + wv.z * xv.z + wv.w * xv.w;
                }
            }
        }
        float bb = bias[tid];
        #pragma unroll
        for (int i = 0; i < 32; i++) {
            int t = m * 32 + i;
            g_wxb[(t * BB + b) * DD + tid] = pacc[i] + bb;
        }
    }
    // h[0] copy
    {
        const float* src = h0 + b * SD + (m * 8) * DD;
        float*       dst = h_p + b * SD + (m * 8) * DD;
        for (int idx = tid; idx < 8 * 64; idx += 256) {
            *(float4*)(dst + idx * 4) = *(const float4*)(src + idx * 4);
        }
    }
}

// =====================================================================
// Kernel 2 — fp16 2-pass HMMA recurrence, split cluster barrier.
//   128 CTAs x 256 thr, cluster 2. CTA: rg = blockIdx>>1
//   (b = rg>>2, sg = rg&3 -> s-rows [16*sg,+16)), rank -> e-half.
// =====================================================================
#define A_OFF 0
#define A_BUFSZ 16896
#define A_LOSZ  8448
#define B_OFF 33792
#define SMEM_MAIN 101376

__global__ __launch_bounds__(256, 1) __cluster_dims__(2, 1, 1)
void selman_main(const float* __restrict__ Wh, const float* __restrict__ h0,
                 const float* __restrict__ C, float* __restrict__ d_out) {
    extern __shared__ char smc[];
    const int tid  = threadIdx.x;
    const int wid  = tid >> 5;
    const int l    = tid & 31;
    const int rg   = blockIdx.x >> 1;     // 0..63
    const int rank = blockIdx.x & 1;      // e-half
    const int b    = rg >> 2;
    const int sg   = rg & 3;
    const int sbase = sg * 16;
    float* h_p = d_out + TBD;

    // ---- B (Wh fp16) into padded SMEM ----
    for (int idx = tid; idx < 128 * 256; idx += 256) {
        int n = idx >> 8, k = idx & 255;
        *(__half*)(smc + B_OFF + n * 528 + k * 2) =
            __float2half(Wh[(128 * rank + n) * DD + k]);
    }
    // ---- A buf0 init from h0 (full 256 k-cols of our 16 rows) ----
    for (int idx = tid; idx < 16 * 256; idx += 256) {
        int row = idx >> 8, k = idx & 255;
        float v = h0[b * SD + (sbase + row) * DD + k];
        __half hi = __float2half(v);
        __half lo = __float2half(v - __half2float(hi));
        *(__half*)(smc + A_OFF + row * 528 + k * 2)          = hi;
        *(__half*)(smc + A_OFF + A_LOSZ + row * 528 + k * 2) = lo;
    }
    __syncthreads();

    const uint32_t sb = smem_u32(smc);

    // ---- preload B regs: br[0..7] = own-half k-chunks, br[8..15] = peer ----
    const uint32_t brow = (uint32_t)(16 * wid + ((l >> 4) << 3) + (l & 7));
    const uint32_t bk   = (uint32_t)(((l >> 3) & 1) << 3);
    const uint32_t bAddr = sb + B_OFF + brow * 528 + bk * 2;
    const uint32_t ownOff  = (uint32_t)(rank * 256);
    const uint32_t peerOff = (uint32_t)((rank ^ 1) * 256);
    uint32_t br[16][4];
    #pragma unroll
    for (int j = 0; j < 8; j++)
        LDSM4(br[j][0], br[j][1], br[j][2], br[j][3], bAddr + ownOff + (uint32_t)j * 32);
    #pragma unroll
    for (int j = 0; j < 8; j++)
        LDSM4(br[8+j][0], br[8+j][1], br[8+j][2], br[8+j][3], bAddr + peerOff + (uint32_t)j * 32);

    // ---- A ldmatrix lane address (m16) ----
    const uint32_t arow = (uint32_t)((l & 7) + (((l >> 3) & 1) << 3));
    const uint32_t acol = (uint32_t)((l >> 4) << 3);
    const uint32_t aBase = sb + A_OFF + arow * 528 + acol * 2;

    // ---- peer A base via mapa ----
    uint32_t peerA;
    asm("mapa.shared::cluster.u32 %0, %1, %2;"
        : "=r"(peerA) : "r"(sb + A_OFF), "r"(rank ^ 1));

    // ---- epilogue mapping ----
    const int row0 = l >> 2;
    const int eg0  = 128 * rank + 16 * wid + 2 * (l & 3);
    const float c0 = C[sbase + row0];
    const float c1 = C[sbase + row0 + 8];

    CLUSTER_ARRIVE();     // matches first in-loop WAIT

    for (int t = 0; t < TT; t++) {
        const int pb = t & 1;

        const float* wp = g_wxb + (t * BB + b) * DD + eg0;
        float2 w0 = __ldg((const float2*)(wp));
        float2 w1 = __ldg((const float2*)(wp + 8));

        const uint32_t aH = aBase + (uint32_t)pb * A_BUFSZ;
        const uint32_t aL = aH + A_LOSZ;
        float acc[8];
        #pragma unroll
        for (int i = 0; i < 8; i++) acc[i] = 0.0f;

        // ---- own-half k-chunks (local data) — overlaps peer skew ----
        #pragma unroll
        for (int j = 0; j < 8; j++) {
            const uint32_t ko = ownOff + (uint32_t)j * 32;
            uint32_t ah0, ah1, ah2, ah3, al0, al1, al2, al3;
            LDSM4(ah0, ah1, ah2, ah3, aH + ko);
            LDSM4(al0, al1, al2, al3, aL + ko);
            MMAF16(acc + 0, ah0, ah1, ah2, ah3, br[j][0], br[j][1]);
            MMAF16(acc + 4, ah0, ah1, ah2, ah3, br[j][2], br[j][3]);
            MMAF16(acc + 0, al0, al1, al2, al3, br[j][0], br[j][1]);
            MMAF16(acc + 4, al0, al1, al2, al3, br[j][2], br[j][3]);
        }

        CLUSTER_WAIT();   // peer's DSMEM writes for buf[pb] now visible

        // ---- peer-half k-chunks ----
        #pragma unroll
        for (int j = 0; j < 8; j++) {
            const uint32_t ko = peerOff + (uint32_t)j * 32;
            uint32_t ah0, ah1, ah2, ah3, al0, al1, al2, al3;
            LDSM4(ah0, ah1, ah2, ah3, aH + ko);
            LDSM4(al0, al1, al2, al3, aL + ko);
            MMAF16(acc + 0, ah0, ah1, ah2, ah3, br[8+j][0], br[8+j][1]);
            MMAF16(acc + 4, ah0, ah1, ah2, ah3, br[8+j][2], br[8+j][3]);
            MMAF16(acc + 0, al0, al1, al2, al3, br[8+j][0], br[8+j][1]);
            MMAF16(acc + 4, al0, al1, al2, al3, br[8+j][2], br[8+j][3]);
        }

        // ---- epilogue ----
        const uint32_t nbOff = (uint32_t)(pb ^ 1) * A_BUFSZ;
        float* hd = h_p + (t + 1) * BSD + b * SD + sbase * DD;

        float v00 = fast_tanh(acc[0] + w0.x);
        float v01 = fast_tanh(acc[1] + w0.y);
        float v02 = fast_tanh(acc[2] + w0.x);
        float v03 = fast_tanh(acc[3] + w0.y);
        float v10 = fast_tanh(acc[4] + w1.x);
        float v11 = fast_tanh(acc[5] + w1.y);
        float v12 = fast_tanh(acc[6] + w1.x);
        float v13 = fast_tanh(acc[7] + w1.y);

        // fp32 h stores
        *(float2*)(hd + row0 * DD + eg0)           = make_float2(v00, v01);
        *(float2*)(hd + row0 * DD + eg0 + 8)       = make_float2(v10, v11);
        *(float2*)(hd + (row0 + 8) * DD + eg0)     = make_float2(v02, v03);
        *(float2*)(hd + (row0 + 8) * DD + eg0 + 8) = make_float2(v12, v13);

        // hi/lo fp16 into next A buffer (local + peer DSMEM)
        {
            __half2 H0 = __floats2half2_rn(v00, v01);
            __half2 H1 = __floats2half2_rn(v02, v03);
            __half2 H2 = __floats2half2_rn(v10, v11);
            __half2 H3 = __floats2half2_rn(v12, v13);
            float2 f0 = __half22float2(H0), f1 = __half22float2(H1);
            float2 f2 = __half22float2(H2), f3 = __half22float2(H3);
            __half2 L0 = __floats2half2_rn(v00 - f0.x, v01 - f0.y);
            __half2 L1 = __floats2half2_rn(v02 - f1.x, v03 - f1.y);
            __half2 L2 = __floats2half2_rn(v10 - f2.x, v11 - f2.y);
            __half2 L3 = __floats2half2_rn(v12 - f3.x, v13 - f3.y);
            uint32_t uH0 = *(uint32_t*)&H0, uH1 = *(uint32_t*)&H1;
            uint32_t uH2 = *(uint32_t*)&H2, uH3 = *(uint32_t*)&H3;
            uint32_t uL0 = *(uint32_t*)&L0, uL1 = *(uint32_t*)&L1;
            uint32_t uL2 = *(uint32_t*)&L2, uL3 = *(uint32_t*)&L3;

            uint32_t o00 = nbOff + (uint32_t)(row0 * 528 + eg0 * 2);
            uint32_t o01 = o00 + 16;                 // +8 cols
            uint32_t o10 = nbOff + (uint32_t)((row0 + 8) * 528 + eg0 * 2);
            uint32_t o11 = o10 + 16;
            *(uint32_t*)(smc + A_OFF + o00)          = uH0;
            *(uint32_t*)(smc + A_OFF + o01)          = uH2;
            *(uint32_t*)(smc + A_OFF + o10)          = uH1;
            *(uint32_t*)(smc + A_OFF + o11)          = uH3;
            *(uint32_t*)(smc + A_OFF + o00 + A_LOSZ) = uL0;
            *(uint32_t*)(smc + A_OFF + o01 + A_LOSZ) = uL2;
            *(uint32_t*)(smc + A_OFF + o10 + A_LOSZ) = uL1;
            *(uint32_t*)(smc + A_OFF + o11 + A_LOSZ) = uL3;
            STS_CLUSTER(peerA + o00,          uH0);
            STS_CLUSTER(peerA + o01,          uH2);
            STS_CLUSTER(peerA + o10,          uH1);
            STS_CLUSTER(peerA + o11,          uH3);
            STS_CLUSTER(peerA + o00 + A_LOSZ, uL0);
            STS_CLUSTER(peerA + o01 + A_LOSZ, uL2);
            STS_CLUSTER(peerA + o10 + A_LOSZ, uL1);
            STS_CLUSTER(peerA + o11 + A_LOSZ, uL3);
        }

        // fused partial C-reduction over our 16 s-rows
        {
            float q0 = v00 * c0 + v02 * c1;
            float q1 = v01 * c0 + v03 * c1;
            float q2 = v10 * c0 + v12 * c1;
            float q3 = v11 * c0 + v13 * c1;
            #pragma unroll
            for (int d = 4; d < 32; d <<= 1) {
                q0 += __shfl_xor_sync(0xffffffffu, q0, d);
                q1 += __shfl_xor_sync(0xffffffffu, q1, d);
                q2 += __shfl_xor_sync(0xffffffffu, q2, d);
                q3 += __shfl_xor_sync(0xffffffffu, q3, d);
            }
            if (l < 4) {
                float* rp = g_red + (((t * BB + b) * 4 + sg) * DD)
                          + 128 * rank + 16 * wid + 2 * l;
                *(float2*)(rp)     = make_float2(q0, q1);
                *(float2*)(rp + 8) = make_float2(q2, q3);
            }
        }

        __syncthreads();      // local A(t+1) visible intra-CTA
        CLUSTER_ARRIVE();     // release DSMEM stores; signal peer
    }
    CLUSTER_WAIT();           // balance final arrive
}

// =====================================================================
// Kernel 3 — out[t][b][e] = (sum of 4 partials) * silu(z)
// =====================================================================
__global__ __launch_bounds__(256, 1)
void selman_fin(const float* __restrict__ z, float* __restrict__ d_out) {
    const int tb = blockIdx.x;           // t*BB + b
    const int e  = threadIdx.x;
    const float* rp = g_red + tb * 4 * DD + e;
    float s = rp[0] + rp[DD] + rp[2 * DD] + rp[3 * DD];
    int o = tb * DD + e;
    d_out[o] = s * silu_f(z[o]);
}

extern "C" void kernel_launch(void* const* d_in, const int* in_sizes, int n_in,
                              void* d_out, int out_size) {
    const float* x    = (const float*)d_in[0];
    const float* z    = (const float*)d_in[1];
    const float* h0   = (const float*)d_in[2];
    const float* Wx   = (const float*)d_in[3];
    const float* Wh   = (const float*)d_in[4];
    const float* bias = (const float*)d_in[5];
    const float* C    = (const float*)d_in[6];
    float* out = (float*)d_out;

    size_t smem_pre = 19456 * sizeof(float);
    cudaFuncSetAttribute(selman_pre, cudaFuncAttributeMaxDynamicSharedMemorySize, (int)smem_pre);
    cudaFuncSetAttribute(selman_main, cudaFuncAttributeMaxDynamicSharedMemorySize, SMEM_MAIN);

    selman_pre<<<128, 256, smem_pre>>>(x, h0, Wx, bias, out);
    selman_main<<<128, 256, SMEM_MAIN>>>(Wh, h0, C, out);
    selman_fin<<<TT * BB, 256>>>(z, out);
}

// round 8
// speedup vs baseline: 5.9531x; 1.2872x over previous
#include <cuda_runtime.h>
#include <cuda_bf16.h>
#include <cuda_fp16.h>
#include <cstdint>
#include <math.h>

#define TT 256
#define BB 16
#define SS 64
#define DD 256
#define SD (SS*DD)          // 16384
#define BSD (BB*SD)         // 262144
#define TBD (TT*BB*DD)      // 1048576

__device__ float g_wxb[TBD];
__device__ float g_red[TT*BB*4*DD];   // partial C-reductions [t][b][sg][e]

// ---------------- helpers ----------------
__device__ __forceinline__ uint32_t smem_u32(const void* p) {
    uint32_t a;
    asm("{ .reg .u64 t; cvta.to.shared.u64 t, %1; cvt.u32.u64 %0, t; }" : "=r"(a) : "l"(p));
    return a;
}
__device__ __forceinline__ float fast_tanh(float x) {
    float ax = fabsf(x);
    float e  = __expf(-2.0f * ax);
    float r  = __fdividef(1.0f - e, 1.0f + e);
    return copysignf(r, x);
}
__device__ __forceinline__ float silu_f(float v) {
    return __fdividef(v, 1.0f + __expf(-v));
}

#define LDSM4(r0, r1, r2, r3, addr) \
    asm volatile("ldmatrix.sync.aligned.m8n8.x4.shared.b16 {%0,%1,%2,%3}, [%4];" \
        : "=r"(r0), "=r"(r1), "=r"(r2), "=r"(r3) : "r"(addr))

#define MMAF16(d, a0, a1, a2, a3, b0, b1) \
    asm volatile("mma.sync.aligned.m16n8k16.row.col.f32.f16.f16.f32 " \
        "{%0,%1,%2,%3}, {%4,%5,%6,%7}, {%8,%9}, {%0,%1,%2,%3};" \
        : "+f"((d)[0]), "+f"((d)[1]), "+f"((d)[2]), "+f"((d)[3]) \
        : "r"(a0), "r"(a1), "r"(a2), "r"(a3), "r"(b0), "r"(b1))

#define CLUSTER_ARRIVE() asm volatile("barrier.cluster.arrive.aligned;" ::: "memory")
#define CLUSTER_WAIT()   asm volatile("barrier.cluster.wait.aligned;" ::: "memory")
#define STS_CLUSTER(addr, val) \
    asm volatile("st.shared::cluster.u32 [%0], %1;" :: "r"(addr), "r"(val) : "memory")

// =====================================================================
// Kernel 1 — prologue: wxb = x@Wx^T + b, h[0] copy.  256 CTAs.
// =====================================================================
__global__ __launch_bounds__(256, 1)
void selman_pre(const float* __restrict__ x, const float* __restrict__ h0,
                const float* __restrict__ Wx, const float* __restrict__ bias,
                float* __restrict__ d_out) {
    extern __shared__ float sm[];
    const int tid = threadIdx.x;
    const int b = blockIdx.x >> 4;
    const int m = blockIdx.x & 15;
    float* h_p = d_out + TBD;

    {   // wxb for t in [16m, 16m+16)
        float* wch = sm;           // [256][68]
        float* xch = sm + 17408;   // [16][64]
        float pacc[16];
        #pragma unroll
        for (int i = 0; i < 16; i++) pacc[i] = 0.0f;
        for (int kt = 0; kt < 4; kt++) {
            const int k0 = kt * 64;
            __syncthreads();
            for (int idx = tid; idx < 256 * 16; idx += 256) {
                int e = idx >> 4, q = idx & 15;
                *(float4*)(wch + e * 68 + q * 4) = *(const float4*)(Wx + e * DD + k0 + q * 4);
            }
            for (int idx = tid; idx < 16 * 16; idx += 256) {
                int i = idx >> 4, q = idx & 15;
                int t = m * 16 + i;
                *(float4*)(xch + i * 64 + q * 4) = *(const float4*)(x + (t * BB + b) * DD + k0 + q * 4);
            }
            __syncthreads();
            for (int q = 0; q < 16; q++) {
                float4 wv = *(const float4*)(wch + tid * 68 + q * 4);
                #pragma unroll
                for (int i = 0; i < 16; i++) {
                    float4 xv = *(const float4*)(xch + i * 64 + q * 4);
                    pacc[i] += wv.x * xv.x + wv.y * xv.y + wv.z * xv.z + wv.w * xv.w;
                }
            }
        }
        float bb = bias[tid];
        #pragma unroll
        for (int i = 0; i < 16; i++) {
            int t = m * 16 + i;
            g_wxb[(t * BB + b) * DD + tid] = pacc[i] + bb;
        }
    }
    // h[0] copy (member m handles s-rows [4m, 4m+4))
    {
        const float* src = h0 + b * SD + (m * 4) * DD;
        float*       dst = h_p + b * SD + (m * 4) * DD;
        for (int idx = tid; idx < 4 * 64; idx += 256) {
            *(float4*)(dst + idx * 4) = *(const float4*)(src + idx * 4);
        }
    }
}

// =====================================================================
// Kernel 2 — fp16 1-pass HMMA recurrence, split cluster barrier.
//   128 CTAs x 256 thr, cluster 2. CTA: rg = blockIdx>>1
//   (b = rg>>2, sg = rg&3 -> s-rows [16*sg,+16)), rank -> e-half.
// =====================================================================
#define A_OFF 0
#define A_BUFSZ 8448            // [16 rows][528 B]
#define B_OFF 16896
#define SMEM_MAIN 84480         // 16896 + 128*528

__global__ __launch_bounds__(256, 1) __cluster_dims__(2, 1, 1)
void selman_main(const float* __restrict__ Wh, const float* __restrict__ h0,
                 const float* __restrict__ C, float* __restrict__ d_out) {
    extern __shared__ char smc[];
    const int tid  = threadIdx.x;
    const int wid  = tid >> 5;
    const int l    = tid & 31;
    const int rg   = blockIdx.x >> 1;     // 0..63
    const int rank = blockIdx.x & 1;      // e-half
    const int b    = rg >> 2;
    const int sg   = rg & 3;
    const int sbase = sg * 16;
    float* h_p = d_out + TBD;

    // ---- B (Wh fp16) into padded SMEM ----
    for (int idx = tid; idx < 128 * 256; idx += 256) {
        int n = idx >> 8, k = idx & 255;
        *(__half*)(smc + B_OFF + n * 528 + k * 2) =
            __float2half(Wh[(128 * rank + n) * DD + k]);
    }
    // ---- A buf0 init from h0 (full 256 k-cols of our 16 rows) ----
    for (int idx = tid; idx < 16 * 256; idx += 256) {
        int row = idx >> 8, k = idx & 255;
        float v = h0[b * SD + (sbase + row) * DD + k];
        *(__half*)(smc + A_OFF + row * 528 + k * 2) = __float2half(v);
    }
    __syncthreads();

    const uint32_t sb = smem_u32(smc);

    // ---- preload B regs: br[0..7] = own-half k-chunks, br[8..15] = peer ----
    const uint32_t brow = (uint32_t)(16 * wid + ((l >> 4) << 3) + (l & 7));
    const uint32_t bk   = (uint32_t)(((l >> 3) & 1) << 3);
    const uint32_t bAddr = sb + B_OFF + brow * 528 + bk * 2;
    const uint32_t ownOff  = (uint32_t)(rank * 256);
    const uint32_t peerOff = (uint32_t)((rank ^ 1) * 256);
    uint32_t br[16][4];
    #pragma unroll
    for (int j = 0; j < 8; j++)
        LDSM4(br[j][0], br[j][1], br[j][2], br[j][3], bAddr + ownOff + (uint32_t)j * 32);
    #pragma unroll
    for (int j = 0; j < 8; j++)
        LDSM4(br[8+j][0], br[8+j][1], br[8+j][2], br[8+j][3], bAddr + peerOff + (uint32_t)j * 32);

    // ---- A ldmatrix lane address (m16) ----
    const uint32_t arow = (uint32_t)((l & 7) + (((l >> 3) & 1) << 3));
    const uint32_t acol = (uint32_t)((l >> 4) << 3);
    const uint32_t aBase = sb + A_OFF + arow * 528 + acol * 2;

    // ---- peer A base via mapa ----
    uint32_t peerA;
    asm("mapa.shared::cluster.u32 %0, %1, %2;"
        : "=r"(peerA) : "r"(sb + A_OFF), "r"(rank ^ 1));

    // ---- epilogue mapping ----
    const int row0 = l >> 2;
    const int eg0  = 128 * rank + 16 * wid + 2 * (l & 3);
    const float c0 = C[sbase + row0];
    const float c1 = C[sbase + row0 + 8];

    CLUSTER_ARRIVE();     // matches first in-loop WAIT

    for (int t = 0; t < TT; t++) {
        const int pb = t & 1;

        const float* wp = g_wxb + (t * BB + b) * DD + eg0;
        float2 w0 = __ldg((const float2*)(wp));
        float2 w1 = __ldg((const float2*)(wp + 8));

        const uint32_t aH = aBase + (uint32_t)pb * A_BUFSZ;
        float acc[8];
        #pragma unroll
        for (int i = 0; i < 8; i++) acc[i] = 0.0f;

        // ---- own-half k-chunks (local data) — overlaps peer skew ----
        #pragma unroll
        for (int j = 0; j < 8; j++) {
            const uint32_t ko = ownOff + (uint32_t)j * 32;
            uint32_t a0, a1, a2, a3;
            LDSM4(a0, a1, a2, a3, aH + ko);
            MMAF16(acc + 0, a0, a1, a2, a3, br[j][0], br[j][1]);
            MMAF16(acc + 4, a0, a1, a2, a3, br[j][2], br[j][3]);
        }

        CLUSTER_WAIT();   // peer's DSMEM writes for buf[pb] now visible

        // ---- peer-half k-chunks ----
        #pragma unroll
        for (int j = 0; j < 8; j++) {
            const uint32_t ko = peerOff + (uint32_t)j * 32;
            uint32_t a0, a1, a2, a3;
            LDSM4(a0, a1, a2, a3, aH + ko);
            MMAF16(acc + 0, a0, a1, a2, a3, br[8+j][0], br[8+j][1]);
            MMAF16(acc + 4, a0, a1, a2, a3, br[8+j][2], br[8+j][3]);
        }

        // ---- epilogue ----
        const uint32_t nbOff = (uint32_t)(pb ^ 1) * A_BUFSZ;
        float* hd = h_p + (t + 1) * BSD + b * SD + sbase * DD;

        float v00 = fast_tanh(acc[0] + w0.x);
        float v01 = fast_tanh(acc[1] + w0.y);
        float v02 = fast_tanh(acc[2] + w0.x);
        float v03 = fast_tanh(acc[3] + w0.y);
        float v10 = fast_tanh(acc[4] + w1.x);
        float v11 = fast_tanh(acc[5] + w1.y);
        float v12 = fast_tanh(acc[6] + w1.x);
        float v13 = fast_tanh(acc[7] + w1.y);

        // fp32 h stores
        *(float2*)(hd + row0 * DD + eg0)           = make_float2(v00, v01);
        *(float2*)(hd + row0 * DD + eg0 + 8)       = make_float2(v10, v11);
        *(float2*)(hd + (row0 + 8) * DD + eg0)     = make_float2(v02, v03);
        *(float2*)(hd + (row0 + 8) * DD + eg0 + 8) = make_float2(v12, v13);

        // fp16 into next A buffer (local + peer DSMEM)
        {
            __half2 H0 = __floats2half2_rn(v00, v01);
            __half2 H1 = __floats2half2_rn(v02, v03);
            __half2 H2 = __floats2half2_rn(v10, v11);
            __half2 H3 = __floats2half2_rn(v12, v13);
            uint32_t uH0 = *(uint32_t*)&H0, uH1 = *(uint32_t*)&H1;
            uint32_t uH2 = *(uint32_t*)&H2, uH3 = *(uint32_t*)&H3;

            uint32_t o00 = nbOff + (uint32_t)(row0 * 528 + eg0 * 2);
            uint32_t o01 = o00 + 16;                 // +8 cols
            uint32_t o10 = nbOff + (uint32_t)((row0 + 8) * 528 + eg0 * 2);
            uint32_t o11 = o10 + 16;
            *(uint32_t*)(smc + A_OFF + o00) = uH0;
            *(uint32_t*)(smc + A_OFF + o01) = uH2;
            *(uint32_t*)(smc + A_OFF + o10) = uH1;
            *(uint32_t*)(smc + A_OFF + o11) = uH3;
            STS_CLUSTER(peerA + o00, uH0);
            STS_CLUSTER(peerA + o01, uH2);
            STS_CLUSTER(peerA + o10, uH1);
            STS_CLUSTER(peerA + o11, uH3);
        }

        // fused partial C-reduction over our 16 s-rows
        {
            float q0 = v00 * c0 + v02 * c1;
            float q1 = v01 * c0 + v03 * c1;
            float q2 = v10 * c0 + v12 * c1;
            float q3 = v11 * c0 + v13 * c1;
            #pragma unroll
            for (int d = 4; d < 32; d <<= 1) {
                q0 += __shfl_xor_sync(0xffffffffu, q0, d);
                q1 += __shfl_xor_sync(0xffffffffu, q1, d);
                q2 += __shfl_xor_sync(0xffffffffu, q2, d);
                q3 += __shfl_xor_sync(0xffffffffu, q3, d);
            }
            if (l < 4) {
                float* rp = g_red + (((t * BB + b) * 4 + sg) * DD)
                          + 128 * rank + 16 * wid + 2 * l;
                *(float2*)(rp)     = make_float2(q0, q1);
                *(float2*)(rp + 8) = make_float2(q2, q3);
            }
        }

        __syncthreads();      // local A(t+1) visible intra-CTA
        CLUSTER_ARRIVE();     // release DSMEM stores; signal peer
    }
    CLUSTER_WAIT();           // balance final arrive
}

// =====================================================================
// Kernel 3 — out[t][b][e] = (sum of 4 partials) * silu(z)
// =====================================================================
__global__ __launch_bounds__(256, 1)
void selman_fin(const float* __restrict__ z, float* __restrict__ d_out) {
    const int tb = blockIdx.x;           // t*BB + b
    const int e  = threadIdx.x;
    const float* rp = g_red + tb * 4 * DD + e;
    float s = rp[0] + rp[DD] + rp[2 * DD] + rp[3 * DD];
    int o = tb * DD + e;
    d_out[o] = s * silu_f(z[o]);
}

extern "C" void kernel_launch(void* const* d_in, const int* in_sizes, int n_in,
                              void* d_out, int out_size) {
    const float* x    = (const float*)d_in[0];
    const float* z    = (const float*)d_in[1];
    const float* h0   = (const float*)d_in[2];
    const float* Wx   = (const float*)d_in[3];
    const float* Wh   = (const float*)d_in[4];
    const float* bias = (const float*)d_in[5];
    const float* C    = (const float*)d_in[6];
    float* out = (float*)d_out;

    size_t smem_pre = 18432 * sizeof(float);
    cudaFuncSetAttribute(selman_pre, cudaFuncAttributeMaxDynamicSharedMemorySize, (int)smem_pre);
    cudaFuncSetAttribute(selman_main, cudaFuncAttributeMaxDynamicSharedMemorySize, SMEM_MAIN);

    selman_pre<<<256, 256, smem_pre>>>(x, h0, Wx, bias, out);
    selman_main<<<128, 256, SMEM_MAIN>>>(Wh, h0, C, out);
    selman_fin<<<TT * BB, 256>>>(z, out);
}